// round 6
// baseline (speedup 1.0000x reference)
#include <cuda_runtime.h>
#include <cstdint>

// Problem constants (match reference)
#define B      32
#define TMAX   512
#define D      384
#define MAXDUR 8
#define TOUT   (TMAX * (MAXDUR - 1))   // 3584
#define VEC    (D / 4)                 // 96 float4 per row
#define ROWS_PER_CTA 8                 // 8 warps, 1 output row each
#define CTAS_PER_B   (TOUT / ROWS_PER_CTA)   // 448
#define NCTAS  (B * CTAS_PER_B)        // 14336
#define CHUNK_BYTES (ROWS_PER_CTA * D * 4)   // 12288

__device__ __forceinline__ uint32_t smem_u32(const void* p) {
    uint32_t a;
    asm("{ .reg .u64 t; cvta.to.shared.u64 t, %1; cvt.u32.u64 %0, t; }"
        : "=r"(a) : "l"(p));
    return a;
}

// ---------------------------------------------------------------------------
// Fused kernel (R4 shape, 256 thr, 8 frames/CTA) with:
//   - binary search done once by warp 0 (lanes 0..7), broadcast via smem
//   - gather LDG -> STS into a 12KB smem buffer (8 contiguous output rows)
//   - single cp.async.bulk S2G of the whole 12KB chunk (async, full-line)
// ---------------------------------------------------------------------------
__global__ void __launch_bounds__(256) lenreg_fused_kernel(
    const float4* __restrict__ xs,     // [B, TMAX, VEC]
    const int*    __restrict__ ds,     // [B, TMAX]
    const int*    __restrict__ ilens,  // [B]
    float4*       __restrict__ out)    // [B, TOUT, VEC]
{
    const int cta    = blockIdx.x;
    const int b      = cta / CTAS_PER_B;              // mul-shift
    const int f_base = (cta - b * CTAS_PER_B) * ROWS_PER_CTA;

    const int t    = threadIdx.x;     // 0..255
    const int lane = t & 31;
    const int wid  = t >> 5;          // 0..7

    __shared__ int    s_cum[TMAX];                    // 2 KB
    __shared__ int    s_wsum[8];
    __shared__ int    s_idx[ROWS_PER_CTA];
    __shared__ __align__(16) float4 s_buf[ROWS_PER_CTA * VEC];  // 12 KB

    const int L = ilens[b];

    // --- block scan: thread t owns elements 2t, 2t+1 -----------------------
    const int e0 = 2 * t;
    const int e1 = 2 * t + 1;
    int d0 = (e0 < L) ? __ldg(ds + b * TMAX + e0) : 0;
    int d1 = (e1 < L) ? __ldg(ds + b * TMAX + e1) : 0;
    int pair = d0 + d1;

    int p = pair;
    #pragma unroll
    for (int off = 1; off < 32; off <<= 1) {
        int v = __shfl_up_sync(0xffffffffu, p, off);
        if (lane >= off) p += v;
    }
    if (lane == 31) s_wsum[wid] = p;
    __syncthreads();

    int woff = 0;
    #pragma unroll
    for (int w = 0; w < 8; ++w)
        woff += (w < wid) ? s_wsum[w] : 0;

    const int excl = p - pair + woff;
    s_cum[e0] = excl + d0;
    s_cum[e1] = excl + d0 + d1;
    __syncthreads();

    int total = s_cum[TMAX - 1];
    if (total == 0) {
        // all-zero fallback: d = mask -> cum[t'] = min(t'+1, L)
        s_cum[e0] = (e0 < L) ? (e0 + 1) : L;
        s_cum[e1] = (e1 < L) ? (e1 + 1) : L;
        total = L;                         // L >= 1 guaranteed
        __syncthreads();
    }

    // --- warp 0: 8 binary searches (one per output frame), broadcast -------
    if (wid == 0 && lane < ROWS_PER_CTA) {
        const int f = f_base + lane;
        // searchsorted(cum, f, side='right'); 10 steps for range [0, 512]
        int lo = 0, hi = TMAX;
        #pragma unroll
        for (int step = 0; step < 10; ++step) {
            int mid = (lo + hi) >> 1;
            if (s_cum[mid] <= f) lo = mid + 1; else hi = mid;
        }
        s_idx[lane] = (lo < TMAX - 1) ? lo : (TMAX - 1);
    }
    __syncthreads();

    // --- per-warp gather into smem buffer -----------------------------------
    const int f = f_base + wid;
    const int i = s_idx[wid];

    float4 r0, r1, r2;
    if (f < total) {
        const float4* src = xs + ((long)b * TMAX + i) * VEC;
        r0 = __ldg(src + lane);
        r1 = __ldg(src + lane + 32);
        r2 = __ldg(src + lane + 64);
    } else {
        r0 = r1 = r2 = make_float4(0.f, 0.f, 0.f, 0.f);
    }
    float4* bw = s_buf + wid * VEC;
    bw[lane]      = r0;
    bw[lane + 32] = r1;
    bw[lane + 64] = r2;
    __syncthreads();

    // --- single bulk async store of the contiguous 12KB chunk ---------------
    if (t == 0) {
        asm volatile("fence.proxy.async.shared::cta;" ::: "memory");
        void* gdst = (void*)(out + ((long)b * TOUT + f_base) * VEC);
        uint32_t saddr = smem_u32(s_buf);
        asm volatile(
            "cp.async.bulk.global.shared::cta.bulk_group [%0], [%1], %2;"
            :: "l"(gdst), "r"(saddr), "r"((int)CHUNK_BYTES) : "memory");
        asm volatile("cp.async.bulk.commit_group;" ::: "memory");
        asm volatile("cp.async.bulk.wait_group 0;" ::: "memory");
    }
}

extern "C" void kernel_launch(void* const* d_in, const int* in_sizes, int n_in,
                              void* d_out, int out_size)
{
    const float* xs    = (const float*)d_in[0];  // [B, TMAX, D] fp32
    const int*   ds    = (const int*)  d_in[1];  // [B, TMAX] int32
    const int*   ilens = (const int*)  d_in[2];  // [B] int32
    float*       out   = (float*)d_out;          // [B, TOUT, D] fp32

    lenreg_fused_kernel<<<NCTAS, 256>>>(
        (const float4*)xs, ds, ilens, (float4*)out);
}

// round 7
// speedup vs baseline: 1.1490x; 1.1490x over previous
#include <cuda_runtime.h>
#include <cstdint>

// Problem constants (match reference)
#define B      32
#define TMAX   512
#define D      384
#define MAXDUR 8
#define TOUT   (TMAX * (MAXDUR - 1))   // 3584
#define VEC    (D / 4)                 // 96 float4 per row
#define ROWS_PER_CTA 8                 // 8 warps, 1 output row each
#define CTAS_PER_B   (TOUT / ROWS_PER_CTA)   // 448
#define NCTAS  (B * CTAS_PER_B)        // 14336

// ---------------------------------------------------------------------------
// Fused kernel (R4 structure — best measured: 29.4us).
// Each CTA (256 thr = 8 warps):
//   1. vectorized int2 load of this batch's durations, mask by ilen,
//      block-scan into smem (shfl warp scan + shfl cross-warp scan)
//   2. all-zero fallback (cum[t] = min(t+1, L))
//   3. each warp binary-searches its frame f (searchsorted right, 10 steps,
//      LDS broadcasts — warp-uniform, one issue slot per instruction)
//   4. warp gathers 96 float4 of xs[b, idx, :] -> out row, streaming stores
// ---------------------------------------------------------------------------
__global__ void __launch_bounds__(256) lenreg_fused_kernel(
    const float4* __restrict__ xs,     // [B, TMAX, VEC]
    const int2*   __restrict__ ds2,    // [B, TMAX/2]  (ds viewed as int2)
    const int*    __restrict__ ilens,  // [B]
    float4*       __restrict__ out)    // [B, TOUT, VEC]
{
    const int cta    = blockIdx.x;
    const int b      = cta / CTAS_PER_B;              // mul-shift
    const int f_base = (cta - b * CTAS_PER_B) * ROWS_PER_CTA;

    const int t    = threadIdx.x;     // 0..255
    const int lane = t & 31;
    const int wid  = t >> 5;          // 0..7

    __shared__ int s_cum[TMAX];       // inclusive cumsum of masked durations
    __shared__ int s_wsum[8];

    const int L = ilens[b];

    // --- block scan: thread t owns elements 2t, 2t+1 (one int2 load) -------
    const int e0 = 2 * t;
    int2 dd = __ldg(ds2 + b * (TMAX / 2) + t);
    int d0 = (e0     < L) ? dd.x : 0;
    int d1 = (e0 + 1 < L) ? dd.y : 0;
    int pair = d0 + d1;

    // warp inclusive scan of pair sums
    int p = pair;
    #pragma unroll
    for (int off = 1; off < 32; off <<= 1) {
        int v = __shfl_up_sync(0xffffffffu, p, off);
        if (lane >= off) p += v;
    }
    if (lane == 31) s_wsum[wid] = p;
    __syncthreads();

    // cross-warp exclusive offset via shfl scan in each warp's lower lanes
    int woff;
    {
        int v = (lane < 8) ? s_wsum[lane] : 0;
        #pragma unroll
        for (int off = 1; off < 8; off <<= 1) {
            int u = __shfl_up_sync(0xffffffffu, v, off);
            if (lane >= off) v += u;
        }
        // inclusive scan of warp sums in lanes 0..7; exclusive offset for
        // this warp = inclusive[wid-1] (0 for wid==0)
        int excl_w = __shfl_sync(0xffffffffu, v, (wid > 0) ? (wid - 1) : 0);
        woff = (wid > 0) ? excl_w : 0;
    }

    const int excl = p - pair + woff;     // exclusive prefix before e0
    s_cum[e0]     = excl + d0;
    s_cum[e0 + 1] = excl + d0 + d1;
    __syncthreads();

    int total = s_cum[TMAX - 1];
    if (total == 0) {
        // all-zero fallback: d = mask -> cum[t'] = min(t'+1, L)
        s_cum[e0]     = (e0     < L) ? (e0 + 1) : L;
        s_cum[e0 + 1] = (e0 + 1 < L) ? (e0 + 2) : L;
        total = L;                         // L >= 1 guaranteed
        __syncthreads();
    }

    // --- per-warp: binary search + gather -----------------------------------
    const int f = f_base + wid;            // this warp's output frame

    // searchsorted(cum, f, side='right'); 10 steps for range [0, 512]
    int lo = 0, hi = TMAX;
    #pragma unroll
    for (int step = 0; step < 10; ++step) {
        int mid = (lo + hi) >> 1;
        if (s_cum[mid] <= f) lo = mid + 1; else hi = mid;
    }
    const int idx = (lo < TMAX - 1) ? lo : (TMAX - 1);

    float4* dst = out + ((long)b * TOUT + f) * VEC;

    if (f < total) {
        const float4* src = xs + ((long)b * TMAX + idx) * VEC;
        float4 r0 = __ldg(src + lane);
        float4 r1 = __ldg(src + lane + 32);
        float4 r2 = __ldg(src + lane + 64);
        __stcs(dst + lane,      r0);
        __stcs(dst + lane + 32, r1);
        __stcs(dst + lane + 64, r2);
    } else {
        const float4 z = make_float4(0.f, 0.f, 0.f, 0.f);
        __stcs(dst + lane,      z);
        __stcs(dst + lane + 32, z);
        __stcs(dst + lane + 64, z);
    }
}

extern "C" void kernel_launch(void* const* d_in, const int* in_sizes, int n_in,
                              void* d_out, int out_size)
{
    const float* xs    = (const float*)d_in[0];  // [B, TMAX, D] fp32
    const int*   ds    = (const int*)  d_in[1];  // [B, TMAX] int32
    const int*   ilens = (const int*)  d_in[2];  // [B] int32
    float*       out   = (float*)d_out;          // [B, TOUT, D] fp32

    lenreg_fused_kernel<<<NCTAS, 256>>>(
        (const float4*)xs, (const int2*)ds, ilens, (float4*)out);
}